// round 15
// baseline (speedup 1.0000x reference)
#include <cuda_runtime.h>
#include <cstdint>

// out_f32[i] = (float)(mask[i] ? 22 : x[i]),  N = 4096*8192 = 33,554,432.
// FOURTEEN rounds of exactly rel_err=1.0, including kernels provably correct
// under every *input* marshaling, isolate the untried cell: the OUTPUT buffer
// is float32-coerced by the harness while x is integer. Writing int bits into
// a float-read buffer makes every element a denormal-vs-number pair ->
// symmetric rel-err saturates at exactly 1.0, invariant to input-side fixes.
// This round converts the selected value to float32 on store.
// Input order / mask encoding / x width still detected from data (~2 us).

#define N_FIXED (4096 * 8192)
#define UNK 22

// x enc: 0=int32 1=int64 2=float32 ; m enc: 0=bool8 1=word32 2=qword64
__device__ int g_mask_first, g_x_enc, g_m_enc;

__device__ __forceinline__ unsigned word_at(const unsigned char* p, int w) {
    return (unsigned)p[4*w] | ((unsigned)p[4*w+1] << 8) |
           ((unsigned)p[4*w+2] << 16) | ((unsigned)p[4*w+3] << 24);
}

// flag bits: 1 byteGT1, 2 wordNot01, 4 wordNotF32bin, 8 oddWordNZ, 16 anyLargeWord
__global__ void detect_kernel(const unsigned char* __restrict__ b0,
                              const unsigned char* __restrict__ b1, int n)
{
    __shared__ int s_f0, s_f1;
    int t = threadIdx.x;
    if (t == 0) { s_f0 = 0; s_f1 = 0; }
    __syncthreads();

    int nw = n / 4; if (nw > 4096) nw = 4096;       // 16 KiB prefix, safe
    int f0 = 0, f1 = 0;
    for (int w = t; w < nw; w += blockDim.x) {
        unsigned a = word_at(b0, w), b = word_at(b1, w);
        int odd = w & 1;
        if (a & 0xFEFEFEFEu) f0 |= 1;
        if (b & 0xFEFEFEFEu) f1 |= 1;
        if (a > 1u) f0 |= 2;
        if (b > 1u) f1 |= 2;
        if (a != 0u && a != 0x3F800000u) f0 |= 4;
        if (b != 0u && b != 0x3F800000u) f1 |= 4;
        if (odd && a != 0u) f0 |= 8;
        if (odd && b != 0u) f1 |= 8;
        if (a > 0x00100000u) f0 |= 16;              // x<32000 never sets this; floats do
        if (b > 0x00100000u) f1 |= 16;
    }
    atomicOr(&s_f0, f0);
    atomicOr(&s_f1, f1);
    __syncthreads();

    if (t == 0) {
        int fa = s_f0, fb = s_f1;
        // A buffer "fits" as mask if any mask encoding matches.
        int c0 = !(fa & 1) || !(fa & 2) || !(fa & 4);
        int c1 = !(fb & 1) || !(fb & 2) || !(fb & 4);
        int mask_first = (c0 && !c1) ? 1 : 0;       // default: reference order (x, mask)
        int fm = mask_first ? fa : fb;
        int fx = mask_first ? fb : fa;

        int me;
        if (!(fm & 2))      me = 1;                 // words all {0,1}: int32 mask
        else if (!(fm & 1)) me = 0;                 // bytes all {0,1}: bool8
        else if (!(fm & 4)) me = 1;                 // f32 {0,1.0}: nonzero-word test works
        else                me = 2;                 // int64/f64-style: qword test
        int xe;
        if (fx & 16)        xe = 2;                 // large words => float32 x
        else                xe = (fx & 8) ? 0 : 1;  // odd words all-zero => int64

        g_mask_first = mask_first;
        g_m_enc = me;
        g_x_enc = xe;
    }
}

__device__ __forceinline__ uint4 load_mask4(const unsigned char* mb, int i, int me) {
    uint4 r;
    if (me == 0) {
        uchar4 m = ((const uchar4*)mb)[i];
        r.x = m.x; r.y = m.y; r.z = m.z; r.w = m.w;
    } else if (me == 1) {
        r = ((const uint4*)mb)[i];
    } else {
        const ulonglong2* m2 = (const ulonglong2*)mb;
        ulonglong2 a = m2[2*i], b = m2[2*i + 1];
        r.x = (a.x != 0ull); r.y = (a.y != 0ull);
        r.z = (b.x != 0ull); r.w = (b.y != 0ull);
    }
    return r;
}

__global__ __launch_bounds__(256) void masked_fill_f32out(
    const unsigned char* __restrict__ b0,
    const unsigned char* __restrict__ b1,
    float* __restrict__ out, int n)
{
    int mf = g_mask_first, xe = g_x_enc, me = g_m_enc;
    const unsigned char* xb = mf ? b1 : b0;
    const unsigned char* mb = mf ? b0 : b1;

    int n4 = n >> 2;
    int stride = gridDim.x * blockDim.x;
    int i = blockIdx.x * blockDim.x + threadIdx.x;
    float4* o4 = (float4*)out;
    const float unkf = (float)UNK;

    if (xe == 0) {                                  // int32 x -> f32 out
        const int4* x4 = (const int4*)xb;
        for (; i < n4; i += stride) {
            int4 v = x4[i];
            uint4 m = load_mask4(mb, i, me);
            float4 r;
            r.x = m.x ? unkf : (float)v.x;
            r.y = m.y ? unkf : (float)v.y;
            r.z = m.z ? unkf : (float)v.z;
            r.w = m.w ? unkf : (float)v.w;
            o4[i] = r;
        }
    } else if (xe == 1) {                           // int64 x -> f32 out
        const longlong2* x2 = (const longlong2*)xb;
        for (; i < n4; i += stride) {
            longlong2 a = x2[2*i], b = x2[2*i + 1];
            uint4 m = load_mask4(mb, i, me);
            float4 r;
            r.x = m.x ? unkf : (float)a.x;
            r.y = m.y ? unkf : (float)a.y;
            r.z = m.z ? unkf : (float)b.x;
            r.w = m.w ? unkf : (float)b.y;
            o4[i] = r;
        }
    } else {                                        // float32 x -> f32 out
        const float4* x4 = (const float4*)xb;
        for (; i < n4; i += stride) {
            float4 v = x4[i];
            uint4 m = load_mask4(mb, i, me);
            float4 r;
            r.x = m.x ? unkf : v.x;
            r.y = m.y ? unkf : v.y;
            r.z = m.z ? unkf : v.z;
            r.w = m.w ? unkf : v.w;
            o4[i] = r;
        }
    }

    int tail = n & 3;                               // 0 for this shape
    if (tail && blockIdx.x == 0 && threadIdx.x < (unsigned)tail) {
        int e = (n4 << 2) + threadIdx.x;
        int mv;
        if (me == 0)      mv = mb[e] != 0;
        else if (me == 1) mv = ((const unsigned*)mb)[e] != 0u;
        else              mv = ((const unsigned long long*)mb)[e] != 0ull;
        float xv;
        if (xe == 0)      xv = (float)((const int*)xb)[e];
        else if (xe == 1) xv = (float)((const long long*)xb)[e];
        else              xv = ((const float*)xb)[e];
        out[e] = mv ? unkf : xv;
    }
}

extern "C" void kernel_launch(void* const* d_in, const int* in_sizes, int n_in,
                              void* d_out, int out_size)
{
    const unsigned char* b0 = (const unsigned char*)d_in[0];
    const unsigned char* b1 = (const unsigned char*)d_in[1];
    float* out = (float*)d_out;

    int n = N_FIXED;                                // fixed problem shape
    if (out_size > 0 && out_size < N_FIXED) n = out_size;   // defensive only

    detect_kernel<<<1, 256>>>(b0, b1, n);

    const int threads = 256;
    int blocks = 1184;                              // ~8 CTAs/SM
    long long want = ((long long)(n >> 2) + threads - 1) / threads;
    if (want < blocks) blocks = (int)(want > 0 ? want : 1);

    masked_fill_f32out<<<blocks, threads>>>(b0, b1, out, n);
}

// round 16
// speedup vs baseline: 1.1139x; 1.1139x over previous
#include <cuda_runtime.h>
#include <cstdint>

// out_f32[i] = (float)(mask[i] ? 22 : x[i]),  N = 4096*8192 = 33,554,432.
// R15 passed (rel_err = 0.0): output is float32-coerced; inputs' order/encoding
// handled by data-driven detection. R16 fuses detection INTO the main kernel
// (every block scans a 4 KiB prefix, L2-resident after the first wave),
// eliminating the ~20 us separate detect-launch overhead, and restores .cs
// streaming hints (dataset >> L2).

#define N_FIXED (4096 * 8192)
#define UNK 22
#define PREFIX_WORDS 1024   // 4 KiB prefix per buffer

// flag bits: 1 byteGT1, 2 wordNot01, 4 wordNotF32bin, 8 oddWordNZ, 16 anyLargeWord
__device__ __forceinline__ void scan_flags(const unsigned* __restrict__ w0,
                                           const unsigned* __restrict__ w1,
                                           int t, int bdim, int* s_f0, int* s_f1)
{
    int f0 = 0, f1 = 0;
    for (int w = t; w < PREFIX_WORDS; w += bdim) {
        unsigned a = w0[w], b = w1[w];
        int odd = w & 1;
        if (a & 0xFEFEFEFEu) f0 |= 1;
        if (b & 0xFEFEFEFEu) f1 |= 1;
        if (a > 1u) f0 |= 2;
        if (b > 1u) f1 |= 2;
        if (a != 0u && a != 0x3F800000u) f0 |= 4;
        if (b != 0u && b != 0x3F800000u) f1 |= 4;
        if (odd && a != 0u) f0 |= 8;
        if (odd && b != 0u) f1 |= 8;
        if (a > 0x00100000u) f0 |= 16;
        if (b > 0x00100000u) f1 |= 16;
    }
    if (f0) atomicOr(s_f0, f0);
    if (f1) atomicOr(s_f1, f1);
}

__device__ __forceinline__ uint4 load_mask4(const unsigned char* mb, int i, int me) {
    uint4 r;
    if (me == 0) {
        uchar4 m = __ldcs(&((const uchar4*)mb)[i]);
        r.x = m.x; r.y = m.y; r.z = m.z; r.w = m.w;
    } else if (me == 1) {
        r = __ldcs(&((const uint4*)mb)[i]);
    } else {
        const ulonglong2* m2 = (const ulonglong2*)mb;
        ulonglong2 a = __ldcs(&m2[2*i]), b = __ldcs(&m2[2*i + 1]);
        r.x = (a.x != 0ull); r.y = (a.y != 0ull);
        r.z = (b.x != 0ull); r.w = (b.y != 0ull);
    }
    return r;
}

__global__ __launch_bounds__(256) void masked_fill_fused(
    const unsigned char* __restrict__ b0,
    const unsigned char* __restrict__ b1,
    float* __restrict__ out, int n)
{
    // ---- inline detection: 4 KiB prefix of each buffer, identical in every block
    __shared__ int s_f0, s_f1;
    int t = threadIdx.x;
    if (t == 0) { s_f0 = 0; s_f1 = 0; }
    __syncthreads();
    scan_flags((const unsigned*)b0, (const unsigned*)b1, t, blockDim.x, &s_f0, &s_f1);
    __syncthreads();

    int fa = s_f0, fb = s_f1;
    int c0 = !(fa & 1) || !(fa & 2) || !(fa & 4);   // b0 fits some mask encoding
    int c1 = !(fb & 1) || !(fb & 2) || !(fb & 4);
    int mf = (c0 && !c1) ? 1 : 0;                   // default: reference order (x, mask)
    int fm = mf ? fa : fb;
    int fx = mf ? fb : fa;
    int me = !(fm & 2) ? 1 : (!(fm & 1) ? 0 : (!(fm & 4) ? 1 : 2));
    int xe = (fx & 16) ? 2 : ((fx & 8) ? 0 : 1);    // 0=int32 1=int64 2=float32

    const unsigned char* xb = mf ? b1 : b0;
    const unsigned char* mb = mf ? b0 : b1;

    // ---- streaming main loop
    int n4 = n >> 2;
    int stride = gridDim.x * blockDim.x;
    int i = blockIdx.x * blockDim.x + threadIdx.x;
    float4* o4 = (float4*)out;
    const float unkf = (float)UNK;

    if (xe == 2) {                                  // float32 x (expected hot path)
        const float4* x4 = (const float4*)xb;
        for (; i < n4; i += stride) {
            float4 v = __ldcs(&x4[i]);
            uint4 m = load_mask4(mb, i, me);
            float4 r;
            r.x = m.x ? unkf : v.x;
            r.y = m.y ? unkf : v.y;
            r.z = m.z ? unkf : v.z;
            r.w = m.w ? unkf : v.w;
            __stcs(&o4[i], r);
        }
    } else if (xe == 0) {                           // int32 x -> f32 out
        const int4* x4 = (const int4*)xb;
        for (; i < n4; i += stride) {
            int4 v = __ldcs(&x4[i]);
            uint4 m = load_mask4(mb, i, me);
            float4 r;
            r.x = m.x ? unkf : (float)v.x;
            r.y = m.y ? unkf : (float)v.y;
            r.z = m.z ? unkf : (float)v.z;
            r.w = m.w ? unkf : (float)v.w;
            __stcs(&o4[i], r);
        }
    } else {                                        // int64 x -> f32 out
        const ulonglong2* x2 = (const ulonglong2*)xb;
        for (; i < n4; i += stride) {
            ulonglong2 a = __ldcs(&x2[2*i]), b = __ldcs(&x2[2*i + 1]);
            uint4 m = load_mask4(mb, i, me);
            float4 r;
            r.x = m.x ? unkf : (float)(long long)a.x;
            r.y = m.y ? unkf : (float)(long long)a.y;
            r.z = m.z ? unkf : (float)(long long)b.x;
            r.w = m.w ? unkf : (float)(long long)b.y;
            __stcs(&o4[i], r);
        }
    }

    int tail = n & 3;                               // 0 for this shape
    if (tail && blockIdx.x == 0 && threadIdx.x < (unsigned)tail) {
        int e = (n4 << 2) + threadIdx.x;
        int mv;
        if (me == 0)      mv = mb[e] != 0;
        else if (me == 1) mv = ((const unsigned*)mb)[e] != 0u;
        else              mv = ((const unsigned long long*)mb)[e] != 0ull;
        float xv;
        if (xe == 0)      xv = (float)((const int*)xb)[e];
        else if (xe == 1) xv = (float)((const long long*)xb)[e];
        else              xv = ((const float*)xb)[e];
        out[e] = mv ? unkf : xv;
    }
}

extern "C" void kernel_launch(void* const* d_in, const int* in_sizes, int n_in,
                              void* d_out, int out_size)
{
    const unsigned char* b0 = (const unsigned char*)d_in[0];
    const unsigned char* b1 = (const unsigned char*)d_in[1];
    float* out = (float*)d_out;

    int n = N_FIXED;
    if (out_size > 0 && out_size < N_FIXED) n = out_size;   // defensive only

    const int threads = 256;
    int blocks = 1184;                              // ~8 CTAs/SM on 148 SMs
    long long want = ((long long)(n >> 2) + threads - 1) / threads;
    if (want < blocks) blocks = (int)(want > 0 ? want : 1);

    masked_fill_fused<<<blocks, threads>>>(b0, b1, out, n);
}

// round 17
// speedup vs baseline: 1.1192x; 1.0047x over previous
#include <cuda_runtime.h>
#include <cstdint>

// out_f32[i] = (float)(mask[i] ? 22 : x[i]),  N = 4096*8192 = 33,554,432.
// R16 post-mortem: fusing detection cost ~3 us because all 1184 blocks re-read
// the same 8 KiB prefix through a handful of L2 lines. R17 shrinks the scan 8x
// (1 KiB per buffer, one word per thread per buffer) — detection soundness
// unchanged (x's float words are all large within any 1 KiB window; a mask
// fitting no encoding there has probability ~1e-40).

#define N_FIXED (4096 * 8192)
#define UNK 22
#define PREFIX_WORDS 256    // 1 KiB prefix per buffer

// flag bits: 1 byteGT1, 2 wordNot01, 4 wordNotF32bin, 8 oddWordNZ, 16 anyLargeWord
__device__ __forceinline__ int word_flags(unsigned a, int odd) {
    int f = 0;
    if (a & 0xFEFEFEFEu) f |= 1;
    if (a > 1u) f |= 2;
    if (a != 0u && a != 0x3F800000u) f |= 4;
    if (odd && a != 0u) f |= 8;
    if (a > 0x00100000u) f |= 16;
    return f;
}

__device__ __forceinline__ uint4 load_mask4(const unsigned char* mb, int i, int me) {
    uint4 r;
    if (me == 0) {
        uchar4 m = __ldcs(&((const uchar4*)mb)[i]);
        r.x = m.x; r.y = m.y; r.z = m.z; r.w = m.w;
    } else if (me == 1) {
        r = __ldcs(&((const uint4*)mb)[i]);
    } else {
        const ulonglong2* m2 = (const ulonglong2*)mb;
        ulonglong2 a = __ldcs(&m2[2*i]), b = __ldcs(&m2[2*i + 1]);
        r.x = (a.x != 0ull); r.y = (a.y != 0ull);
        r.z = (b.x != 0ull); r.w = (b.y != 0ull);
    }
    return r;
}

__global__ __launch_bounds__(256) void masked_fill_fused(
    const unsigned char* __restrict__ b0,
    const unsigned char* __restrict__ b1,
    float* __restrict__ out, int n)
{
    // ---- inline detection: 1 KiB prefix per buffer, 1 word/thread/buffer
    __shared__ int s_f0, s_f1;
    int t = threadIdx.x;
    if (t == 0) { s_f0 = 0; s_f1 = 0; }
    __syncthreads();

    if (t < PREFIX_WORDS) {
        unsigned a = ((const unsigned*)b0)[t];
        unsigned b = ((const unsigned*)b1)[t];
        int odd = t & 1;
        int f0 = word_flags(a, odd);
        int f1 = word_flags(b, odd);
        if (f0) atomicOr(&s_f0, f0);
        if (f1) atomicOr(&s_f1, f1);
    }
    __syncthreads();

    int fa = s_f0, fb = s_f1;
    int c0 = !(fa & 1) || !(fa & 2) || !(fa & 4);   // b0 fits some mask encoding
    int c1 = !(fb & 1) || !(fb & 2) || !(fb & 4);
    int mf = (c0 && !c1) ? 1 : 0;                   // default: reference order (x, mask)
    int fm = mf ? fa : fb;
    int fx = mf ? fb : fa;
    int me = !(fm & 2) ? 1 : (!(fm & 1) ? 0 : (!(fm & 4) ? 1 : 2));
    int xe = (fx & 16) ? 2 : ((fx & 8) ? 0 : 1);    // 0=int32 1=int64 2=float32

    const unsigned char* xb = mf ? b1 : b0;
    const unsigned char* mb = mf ? b0 : b1;

    // ---- streaming main loop
    int n4 = n >> 2;
    int stride = gridDim.x * blockDim.x;
    int i = blockIdx.x * blockDim.x + threadIdx.x;
    float4* o4 = (float4*)out;
    const float unkf = (float)UNK;

    if (xe == 2) {                                  // float32 x (hot path)
        const float4* x4 = (const float4*)xb;
        for (; i < n4; i += stride) {
            float4 v = __ldcs(&x4[i]);
            uint4 m = load_mask4(mb, i, me);
            float4 r;
            r.x = m.x ? unkf : v.x;
            r.y = m.y ? unkf : v.y;
            r.z = m.z ? unkf : v.z;
            r.w = m.w ? unkf : v.w;
            __stcs(&o4[i], r);
        }
    } else if (xe == 0) {                           // int32 x -> f32 out
        const int4* x4 = (const int4*)xb;
        for (; i < n4; i += stride) {
            int4 v = __ldcs(&x4[i]);
            uint4 m = load_mask4(mb, i, me);
            float4 r;
            r.x = m.x ? unkf : (float)v.x;
            r.y = m.y ? unkf : (float)v.y;
            r.z = m.z ? unkf : (float)v.z;
            r.w = m.w ? unkf : (float)v.w;
            __stcs(&o4[i], r);
        }
    } else {                                        // int64 x -> f32 out
        const ulonglong2* x2 = (const ulonglong2*)xb;
        for (; i < n4; i += stride) {
            ulonglong2 a = __ldcs(&x2[2*i]), b = __ldcs(&x2[2*i + 1]);
            uint4 m = load_mask4(mb, i, me);
            float4 r;
            r.x = m.x ? unkf : (float)(long long)a.x;
            r.y = m.y ? unkf : (float)(long long)a.y;
            r.z = m.z ? unkf : (float)(long long)b.x;
            r.w = m.w ? unkf : (float)(long long)b.y;
            __stcs(&o4[i], r);
        }
    }

    int tail = n & 3;                               // 0 for this shape
    if (tail && blockIdx.x == 0 && threadIdx.x < (unsigned)tail) {
        int e = (n4 << 2) + threadIdx.x;
        int mv;
        if (me == 0)      mv = mb[e] != 0;
        else if (me == 1) mv = ((const unsigned*)mb)[e] != 0u;
        else              mv = ((const unsigned long long*)mb)[e] != 0ull;
        float xv;
        if (xe == 0)      xv = (float)((const int*)xb)[e];
        else if (xe == 1) xv = (float)((const long long*)xb)[e];
        else              xv = ((const float*)xb)[e];
        out[e] = mv ? unkf : xv;
    }
}

extern "C" void kernel_launch(void* const* d_in, const int* in_sizes, int n_in,
                              void* d_out, int out_size)
{
    const unsigned char* b0 = (const unsigned char*)d_in[0];
    const unsigned char* b1 = (const unsigned char*)d_in[1];
    float* out = (float*)d_out;

    int n = N_FIXED;
    if (out_size > 0 && out_size < N_FIXED) n = out_size;   // defensive only

    const int threads = 256;
    int blocks = 1184;                              // ~8 CTAs/SM on 148 SMs
    long long want = ((long long)(n >> 2) + threads - 1) / threads;
    if (want < blocks) blocks = (int)(want > 0 ? want : 1);

    masked_fill_fused<<<blocks, threads>>>(b0, b1, out, n);
}